// round 11
// baseline (speedup 1.0000x reference)
#include <cuda_runtime.h>
#include <cstdint>

#define Bb   4
#define NN   2048
#define FIN  256
#define FOUT 128
#define HH   4
#define NEG  0.2f
#define TKI  32          // j per mainloop iteration
#define NI   (NN / TKI)  // 64

// ---------------------------------------------------------------------------
// scratch (no cudaMalloc allowed)
// ---------------------------------------------------------------------------
__device__ float2   g_iAC[Bb * HH * NN];         // (e^el, e^.2el) per (b,h,i)
__device__ float2   g_jEFi[Bb * NN * HH];        // (e^er, e^.2er), [(b*NN+n)*4+h]
__device__ float2   g_irow[Bb * HH * NN];        // prescaled (A*0.25/Z, C*0.25/Z)
__device__ uint32_t g_adjbits[NN * 64];          // 512 KB
__device__ uint4    g_Bfrag4[Bb * (NN / 32) * 1024]; // Wh B-fragments (tf32)

// ---------------------------------------------------------------------------
__device__ __forceinline__ uint32_t f2tf32(float f) {
    uint32_t u;
    asm("cvt.rna.tf32.f32 %0, %1;" : "=r"(u) : "f"(f));
    return u;
}
__device__ __forceinline__ void mma_tf32(float& c0, float& c1, float& c2, float& c3,
                                         uint32_t a0, uint32_t a1, uint32_t a2, uint32_t a3,
                                         uint32_t b0, uint32_t b1) {
    asm volatile("mma.sync.aligned.m16n8k8.row.col.f32.tf32.tf32.f32 "
                 "{%0,%1,%2,%3}, {%4,%5,%6,%7}, {%8,%9}, {%0,%1,%2,%3};"
                 : "+f"(c0), "+f"(c1), "+f"(c2), "+f"(c3)
                 : "r"(a0), "r"(a1), "r"(a2), "r"(a3), "r"(b0), "r"(b1));
}
__device__ __forceinline__ void cp_async16(uint32_t dst, const void* src) {
    asm volatile("cp.async.cg.shared.global [%0], [%1], 16;" :: "r"(dst), "l"(src));
}
#define CP_COMMIT() asm volatile("cp.async.commit_group;" ::: "memory")
#define CP_WAIT0()  asm volatile("cp.async.wait_group 0;" ::: "memory")

// ---------------------------------------------------------------------------
// Kernel 0: adj -> bitmask
// ---------------------------------------------------------------------------
__global__ __launch_bounds__(64) void adjbits_kernel(const int* __restrict__ adj)
{
    const int row = blockIdx.x, w = threadIdx.x;
    const int4* p = (const int4*)(adj + (size_t)row * NN + w * 32);
    uint32_t bits = 0;
#pragma unroll
    for (int q = 0; q < 8; q++) {
        int4 v = __ldg(p + q);
        bits |= (v.x ? 1u : 0u) << (q * 4 + 0);
        bits |= (v.y ? 1u : 0u) << (q * 4 + 1);
        bits |= (v.z ? 1u : 0u) << (q * 4 + 2);
        bits |= (v.w ? 1u : 0u) << (q * 4 + 3);
    }
    g_adjbits[row * 64 + w] = bits;
}

// ---------------------------------------------------------------------------
// Kernel 1 (fused): Wh tile GEMM + B-fragment emit + el/er exps.
// 512 threads: GEMM thread = 2 rows x 4 cols (2048 FMA).
// ---------------------------------------------------------------------------
__global__ __launch_bounds__(512) void wh_fused(const float* __restrict__ hsrc,
                                                const float* __restrict__ Ww,
                                                const float* __restrict__ Wb,
                                                const float* __restrict__ attn_w)
{
    __shared__ float Bs[32][128];    // Ww^T slab (per kb)
    __shared__ float Whs[32][128];   // output tile
    const int t     = threadIdx.x;   // 0..511
    const int grow0 = blockIdx.x * 32;
    const int col   = (t & 31) * 4;
    const int rl0   = (t >> 5) * 2;  // 2 rows per thread

    float acc[2][4];
#pragma unroll
    for (int r = 0; r < 2; r++)
#pragma unroll
        for (int c = 0; c < 4; c++) acc[r][c] = 0.f;

    const float* hr0 = hsrc + (size_t)(grow0 + rl0 + 0) * FIN;
    const float* hr1 = hsrc + (size_t)(grow0 + rl0 + 1) * FIN;

    for (int kb = 0; kb < FIN; kb += 32) {
        {   // stage Bs = Ww^T slab: 512 thr x 2 float4
            int o = t >> 2, kh = (t & 3) * 8;
#pragma unroll
            for (int s2 = 0; s2 < 2; s2++) {
                float4 v = __ldg((const float4*)(Ww + (size_t)o * FIN + kb + kh + s2 * 4));
                Bs[kh + s2 * 4 + 0][o] = v.x;
                Bs[kh + s2 * 4 + 1][o] = v.y;
                Bs[kh + s2 * 4 + 2][o] = v.z;
                Bs[kh + s2 * 4 + 3][o] = v.w;
            }
        }
        __syncthreads();
#pragma unroll
        for (int k4 = 0; k4 < 32; k4 += 4) {
            float4 a0 = __ldg((const float4*)(hr0 + kb + k4));
            float4 a1 = __ldg((const float4*)(hr1 + kb + k4));
            float4 b0 = *(const float4*)&Bs[k4 + 0][col];
            float4 b1 = *(const float4*)&Bs[k4 + 1][col];
            float4 b2 = *(const float4*)&Bs[k4 + 2][col];
            float4 b3 = *(const float4*)&Bs[k4 + 3][col];
#define FMA2(ar, bv) \
            acc[0][0] += a0.ar * bv.x; acc[0][1] += a0.ar * bv.y; \
            acc[0][2] += a0.ar * bv.z; acc[0][3] += a0.ar * bv.w; \
            acc[1][0] += a1.ar * bv.x; acc[1][1] += a1.ar * bv.y; \
            acc[1][2] += a1.ar * bv.z; acc[1][3] += a1.ar * bv.w;
            FMA2(x, b0) FMA2(y, b1) FMA2(z, b2) FMA2(w, b3)
#undef FMA2
        }
        __syncthreads();
    }

    {
        float4 bias = __ldg((const float4*)(Wb + col));
#pragma unroll
        for (int r = 0; r < 2; r++) {
            float4 o4 = make_float4(acc[r][0] + bias.x, acc[r][1] + bias.y,
                                    acc[r][2] + bias.z, acc[r][3] + bias.w);
            *(float4*)&Whs[rl0 + r][col] = o4;
        }
    }
    __syncthreads();

    const int b  = grow0 >> 11;
    const int n0 = grow0 & (NN - 1);

    // (a) emit B-fragments (tf32): 1024 slots, 512 thr x 2
    {
        const size_t base = ((size_t)b * (NN / 32) + (n0 >> 5)) * 1024;
#pragma unroll
        for (int q = 0; q < 2; q++) {
            const int s    = q * 512 + t;
            const int lane = s & 31;
            const int ntp  = (s >> 5) & 7;
            const int ks   = s >> 8;
            const int jl   = ks * 8 + (lane & 3);
            const int o0   = ntp * 16 + (lane >> 2);
            g_Bfrag4[base + s] = make_uint4(f2tf32(Whs[jl][o0]),
                                            f2tf32(Whs[jl + 4][o0]),
                                            f2tf32(Whs[jl][o0 + 8]),
                                            f2tf32(Whs[jl + 4][o0 + 8]));
        }
    }

    // (b) el/er dots + exps (exact fp32): 16 warps x 2 rows
    {
        const int w    = t >> 5;
        const int lane = t & 31;
        float4 al[HH], ar[HH];
#pragma unroll
        for (int hh = 0; hh < HH; hh++) {
            al[hh] = __ldg((const float4*)(attn_w + hh * 2 * FOUT + lane * 4));
            ar[hh] = __ldg((const float4*)(attn_w + hh * 2 * FOUT + FOUT + lane * 4));
        }
#pragma unroll
        for (int r = 0; r < 2; r++) {
            const int rowl = w * 2 + r;
            const int n    = n0 + rowl;
            float4 v = *(const float4*)&Whs[rowl][lane * 4];
#pragma unroll
            for (int hh = 0; hh < HH; hh++) {
                float sl = v.x * al[hh].x + v.y * al[hh].y
                         + v.z * al[hh].z + v.w * al[hh].w;
                float sr = v.x * ar[hh].x + v.y * ar[hh].y
                         + v.z * ar[hh].z + v.w * ar[hh].w;
#pragma unroll
                for (int off = 16; off > 0; off >>= 1) {
                    sl += __shfl_xor_sync(0xffffffffu, sl, off);
                    sr += __shfl_xor_sync(0xffffffffu, sr, off);
                }
                if (lane == 0) {
                    g_iAC[(b * HH + hh) * NN + n] =
                        make_float2(expf(sl), expf(NEG * sl));
                    g_jEFi[((size_t)(b * NN + n)) * HH + hh] =
                        make_float2(expf(sr), expf(NEG * sr));
                }
            }
        }
    }
}

// ---------------------------------------------------------------------------
// Kernel 2: Z pre-pass (smem-tiled j-stream, max-trick).
// ---------------------------------------------------------------------------
__device__ __forceinline__ uint32_t zswz(uint32_t a) {
    return a ^ (((a >> 10) & 7u) << 5);
}
__global__ __launch_bounds__(256) void zsum_kernel()
{
    __shared__ float4 jef[512];
    __shared__ float  zr[32][4][8];
    const int t  = threadIdx.x;
    const int b  = blockIdx.y;
    const int i0 = blockIdx.x * 32;
    const int i  = t >> 3, jq = t & 7;
    const int gi = i0 + i;

    float2 AC[4];
#pragma unroll
    for (int h = 0; h < HH; h++) AC[h] = __ldg(&g_iAC[(b * HH + h) * NN + gi]);

    float z0 = 0.f, z1 = 0.f, z2 = 0.f, z3 = 0.f;
    const float4*   src4 = (const float4*)(g_jEFi + (size_t)b * NN * HH);
    const uint32_t* mrow = g_adjbits + (size_t)gi * 64;
    char* jefc = (char*)jef;

    for (int c0 = 0; c0 < NN; c0 += 256) {
        __syncthreads();
        {
            float4 v0 = __ldg(src4 + (size_t)(c0 + t) * 2);
            float4 v1 = __ldg(src4 + (size_t)(c0 + t) * 2 + 1);
            uint32_t a = zswz((uint32_t)t * 32u);
            *(float4*)(jefc + a)      = v0;
            *(float4*)(jefc + a + 16) = v1;
        }
        __syncthreads();

        const uint32_t mw = __ldg(mrow + (c0 >> 5) + jq);
#pragma unroll 8
        for (int e = 0; e < 32; e++) {
            if ((mw >> e) & 1u) {
                uint32_t a = zswz((uint32_t)(jq * 32 + e) * 32u);
                float4 q01 = *(const float4*)(jefc + a);
                float4 q23 = *(const float4*)(jefc + a + 16);
                z0 += fmaxf(AC[0].x * q01.x, AC[0].y * q01.y);
                z1 += fmaxf(AC[1].x * q01.z, AC[1].y * q01.w);
                z2 += fmaxf(AC[2].x * q23.x, AC[2].y * q23.y);
                z3 += fmaxf(AC[3].x * q23.z, AC[3].y * q23.w);
            }
        }
    }
    __syncthreads();
    zr[i][0][jq] = z0; zr[i][1][jq] = z1; zr[i][2][jq] = z2; zr[i][3][jq] = z3;
    __syncthreads();

    if (t < 128) {
        const int ii = t >> 2, h = t & 3;
        float Z = 0.f;
#pragma unroll
        for (int g = 0; g < 8; g++) Z += zr[ii][h][g];
        float2 ac  = __ldg(&g_iAC[(b * HH + h) * NN + i0 + ii]);
        float  inv = (Z > 0.f) ? 0.25f / Z : 0.f;
        g_irow[(b * HH + h) * NN + i0 + ii] = make_float2(ac.x * inv, ac.y * inv);
    }
}

// ---------------------------------------------------------------------------
// Kernel 3 (main): P_avg @ Wh via mma.sync tf32, M=32, TK=32/iter.
// Warp tile m32 x n32 with ks-split: warp (nw, kh) does ks {2kh, 2kh+1} for
// BOTH m16 tiles -> 8 LDS.128 per 16 MMA. Epilogue adds the two kh-halves.
// smem 38KB: Af 4K | Bf 2x16K (reused as 16K reduce buf) | JP 2x1K.
// ---------------------------------------------------------------------------
#define SM_A(mt, ks, ln)     (((mt) * 4 + (ks)) * 32 + (ln))
#define SM_B(p, ks, ntp, ln) ((p) * 1024 + (ks) * 256 + (ntp) * 32 + (ln))
#define OFF_BF 4096
#define OFF_JP 36864
#define SMEM_BYTES 38912

__global__ __launch_bounds__(256, 3) void gat_main_mma(float* __restrict__ out)
{
    extern __shared__ char smem[];
    uint4*  Af  = (uint4*)smem;
    uint4*  Bf  = (uint4*)(smem + OFF_BF);
    float4* JPf = (float4*)(smem + OFF_JP);
    const uint32_t Bf_sa = (uint32_t)__cvta_generic_to_shared(Bf);
    const uint32_t JP_sa = (uint32_t)__cvta_generic_to_shared(JPf);

    const int t    = threadIdx.x;
    const int w    = t >> 5;
    const int lane = t & 31;
    const int kh   = w >> 2;            // consume: ks half; gen: m16 tile
    const int nw   = w & 3;             // consume: 32-col group; gen: ks
    const int b    = blockIdx.y;
    const int i0   = blockIdx.x * 32;

    const int r = lane >> 2;
    const int c = lane & 3;

    const int gia = i0 + kh * 16 + r;   // generator rows (mt = kh)
    const int gib = gia + 8;

    float2 RA[4], RB[4];
#pragma unroll
    for (int h = 0; h < HH; h++) {
        RA[h] = __ldg(&g_irow[(b * HH + h) * NN + gia]);
        RB[h] = __ldg(&g_irow[(b * HH + h) * NN + gib]);
    }
    const uint32_t* mba   = g_adjbits + (size_t)gia * 64;
    const uint32_t* mbb   = g_adjbits + (size_t)gib * 64;
    const uint4*    bbase = g_Bfrag4 + (size_t)b * (NN / 32) * 1024;
    const float4*   jsrc  = (const float4*)(g_jEFi + (size_t)b * NN * HH);

    float acc[2][4][4];
#pragma unroll
    for (int m = 0; m < 2; m++)
#pragma unroll
        for (int n = 0; n < 4; n++)
#pragma unroll
            for (int k = 0; k < 4; k++) acc[m][n][k] = 0.f;

    auto stage = [&](int jn, int q) {
        const uint4* src = bbase + (size_t)jn * 1024;
        const uint32_t bdst = Bf_sa + (uint32_t)q * 16384u;
#pragma unroll
        for (int k4 = 0; k4 < 4; k4++)
            cp_async16(bdst + (uint32_t)(k4 * 256 + t) * 16u, src + k4 * 256 + t);
        if (t < 64)
            cp_async16(JP_sa + (uint32_t)(q * 64 + t) * 16u, jsrc + jn * 64 + t);
        CP_COMMIT();
    };

    // each warp generates ONE fragment: (mt = kh, ks = nw)
    auto agen = [&](int p, uint32_t ma, uint32_t mb2) {
        const float4* JP = JPf + p * 64;
        const int jA = nw * 8 + c;
        float4 a01 = JP[jA * 2],       a23 = JP[jA * 2 + 1];
        float4 b01 = JP[(jA + 4) * 2], b23 = JP[(jA + 4) * 2 + 1];

        float vaA = (fmaxf(RA[0].x * a01.x, RA[0].y * a01.y)
                   + fmaxf(RA[1].x * a01.z, RA[1].y * a01.w))
                  + (fmaxf(RA[2].x * a23.x, RA[2].y * a23.y)
                   + fmaxf(RA[3].x * a23.z, RA[3].y * a23.w));
        float vbA = (fmaxf(RB[0].x * a01.x, RB[0].y * a01.y)
                   + fmaxf(RB[1].x * a01.z, RB[1].y * a01.w))
                  + (fmaxf(RB[2].x * a23.x, RB[2].y * a23.y)
                   + fmaxf(RB[3].x * a23.z, RB[3].y * a23.w));
        float vaB = (fmaxf(RA[0].x * b01.x, RA[0].y * b01.y)
                   + fmaxf(RA[1].x * b01.z, RA[1].y * b01.w))
                  + (fmaxf(RA[2].x * b23.x, RA[2].y * b23.y)
                   + fmaxf(RA[3].x * b23.z, RA[3].y * b23.w));
        float vbB = (fmaxf(RB[0].x * b01.x, RB[0].y * b01.y)
                   + fmaxf(RB[1].x * b01.z, RB[1].y * b01.w))
                  + (fmaxf(RB[2].x * b23.x, RB[2].y * b23.y)
                   + fmaxf(RB[3].x * b23.z, RB[3].y * b23.w));

        const int sh = nw * 8 + c;
        vaA = ((ma  >> sh)       & 1u) ? vaA : 0.f;
        vbA = ((mb2 >> sh)       & 1u) ? vbA : 0.f;
        vaB = ((ma  >> (sh + 4)) & 1u) ? vaB : 0.f;
        vbB = ((mb2 >> (sh + 4)) & 1u) ? vbB : 0.f;

        Af[SM_A(kh, nw, lane)] =
            make_uint4(f2tf32(vaA), f2tf32(vbA), f2tf32(vaB), f2tf32(vbB));
    };

    auto consume = [&](int p) {
#pragma unroll
        for (int ks2 = 0; ks2 < 2; ks2++) {
            const int ks = kh * 2 + ks2;
            uint4 a0 = Af[SM_A(0, ks, lane)];
            uint4 a1 = Af[SM_A(1, ks, lane)];
            uint4 b0 = Bf[SM_B(p, ks, nw * 2 + 0, lane)];
            uint4 b1 = Bf[SM_B(p, ks, nw * 2 + 1, lane)];
            mma_tf32(acc[0][0][0], acc[0][0][1], acc[0][0][2], acc[0][0][3],
                     a0.x, a0.y, a0.z, a0.w, b0.x, b0.y);
            mma_tf32(acc[0][1][0], acc[0][1][1], acc[0][1][2], acc[0][1][3],
                     a0.x, a0.y, a0.z, a0.w, b0.z, b0.w);
            mma_tf32(acc[0][2][0], acc[0][2][1], acc[0][2][2], acc[0][2][3],
                     a0.x, a0.y, a0.z, a0.w, b1.x, b1.y);
            mma_tf32(acc[0][3][0], acc[0][3][1], acc[0][3][2], acc[0][3][3],
                     a0.x, a0.y, a0.z, a0.w, b1.z, b1.w);
            mma_tf32(acc[1][0][0], acc[1][0][1], acc[1][0][2], acc[1][0][3],
                     a1.x, a1.y, a1.z, a1.w, b0.x, b0.y);
            mma_tf32(acc[1][1][0], acc[1][1][1], acc[1][1][2], acc[1][1][3],
                     a1.x, a1.y, a1.z, a1.w, b0.z, b0.w);
            mma_tf32(acc[1][2][0], acc[1][2][1], acc[1][2][2], acc[1][2][3],
                     a1.x, a1.y, a1.z, a1.w, b1.x, b1.y);
            mma_tf32(acc[1][3][0], acc[1][3][1], acc[1][3][2], acc[1][3][3],
                     a1.x, a1.y, a1.z, a1.w, b1.z, b1.w);
        }
    };

    // prologue
    stage(0, 0);
    uint32_t maC = __ldg(mba + 0);
    uint32_t mbC = __ldg(mbb + 0);
    CP_WAIT0();
    __syncthreads();

    // pipelined mainloop
    for (int jt = 0; jt < NI; jt++) {
        const int p = jt & 1, q = p ^ 1;

        if (jt + 1 < NI) stage(jt + 1, q);

        agen(p, maC, mbC);
        __syncthreads();                 // Af visible

        consume(p);

        if (jt + 1 < NI) {
            maC = __ldg(mba + jt + 1);
            mbC = __ldg(mbb + jt + 1);
            CP_WAIT0();
        }
        __syncthreads();                 // buffer q ready; Af free
    }

    // epilogue: combine kh halves via smem (reuse Bf region), ReLU, store
    float* red = (float*)(smem + OFF_BF);   // 16 KB: [q=mt*4+nt][128][4]
    if (kh == 1) {
#pragma unroll
        for (int mt = 0; mt < 2; mt++)
#pragma unroll
            for (int nt = 0; nt < 4; nt++) {
                const int qn = mt * 4 + nt;
                *(float4*)&red[(qn * 128 + nw * 32 + lane) * 4] =
                    make_float4(acc[mt][nt][0], acc[mt][nt][1],
                                acc[mt][nt][2], acc[mt][nt][3]);
            }
    }
    __syncthreads();
    if (kh == 0) {
#pragma unroll
        for (int mt = 0; mt < 2; mt++) {
            const int row = i0 + mt * 16 + r;
#pragma unroll
            for (int nt = 0; nt < 4; nt++) {
                const int qn = mt * 4 + nt;
                float4 o4 = *(const float4*)&red[(qn * 128 + nw * 32 + lane) * 4];
                const int col = nw * 32 + nt * 8 + c * 2;
                float* op = out + ((size_t)(b * NN + row)) * FOUT + col;
                *(float2*)op =
                    make_float2(fmaxf(acc[mt][nt][0] + o4.x, 0.f),
                                fmaxf(acc[mt][nt][1] + o4.y, 0.f));
                *(float2*)(op + 8 * FOUT) =
                    make_float2(fmaxf(acc[mt][nt][2] + o4.z, 0.f),
                                fmaxf(acc[mt][nt][3] + o4.w, 0.f));
            }
        }
    }
}

// ---------------------------------------------------------------------------
extern "C" void kernel_launch(void* const* d_in, const int* in_sizes, int n_in,
                              void* d_out, int out_size)
{
    const float* h      = (const float*)d_in[0];
    const int*   adj    = (const int*)d_in[1];
    const float* W_w    = (const float*)d_in[2];
    const float* W_b    = (const float*)d_in[3];
    const float* attn_w = (const float*)d_in[4];
    float* out = (float*)d_out;

    adjbits_kernel<<<NN, 64>>>(adj);
    wh_fused<<<(Bb * NN) / 32, 512>>>(h, W_w, W_b, attn_w);
    zsum_kernel<<<dim3(NN / 32, Bb), 256>>>();

    cudaFuncSetAttribute(gat_main_mma,
                         cudaFuncAttributeMaxDynamicSharedMemorySize, SMEM_BYTES);
    gat_main_mma<<<dim3(NN / 32, Bb), 256, SMEM_BYTES>>>(out);
}

// round 12
// speedup vs baseline: 1.0138x; 1.0138x over previous
#include <cuda_runtime.h>
#include <cstdint>

#define Bb   4
#define NN   2048
#define FIN  256
#define FOUT 128
#define HH   4
#define NEG  0.2f
#define TKI  32          // j per mainloop iteration
#define NIH  32          // iterations per CTA (half of 64: split-K)

// ---------------------------------------------------------------------------
// scratch (no cudaMalloc allowed)
// ---------------------------------------------------------------------------
__device__ float2   g_iAC[Bb * HH * NN];         // (e^el, e^.2el) per (b,h,i)
__device__ float2   g_jEFi[Bb * NN * HH];        // (e^er, e^.2er), [(b*NN+n)*4+h]
__device__ float2   g_irow[Bb * HH * NN];        // prescaled (A*0.25/Z, C*0.25/Z)
__device__ uint32_t g_adjbits[NN * 64];          // 512 KB
__device__ uint4    g_Bfrag4[Bb * (NN / 32) * 1024]; // Wh B-fragments (tf32)
__device__ float    g_part[2][Bb * NN * FOUT];   // split-K partials (2 x 4 MB)

// ---------------------------------------------------------------------------
__device__ __forceinline__ uint32_t f2tf32(float f) {
    uint32_t u;
    asm("cvt.rna.tf32.f32 %0, %1;" : "=r"(u) : "f"(f));
    return u;
}
__device__ __forceinline__ void mma_tf32(float& c0, float& c1, float& c2, float& c3,
                                         uint32_t a0, uint32_t a1, uint32_t a2, uint32_t a3,
                                         uint32_t b0, uint32_t b1) {
    asm volatile("mma.sync.aligned.m16n8k8.row.col.f32.tf32.tf32.f32 "
                 "{%0,%1,%2,%3}, {%4,%5,%6,%7}, {%8,%9}, {%0,%1,%2,%3};"
                 : "+f"(c0), "+f"(c1), "+f"(c2), "+f"(c3)
                 : "r"(a0), "r"(a1), "r"(a2), "r"(a3), "r"(b0), "r"(b1));
}
__device__ __forceinline__ void cp_async16(uint32_t dst, const void* src) {
    asm volatile("cp.async.cg.shared.global [%0], [%1], 16;" :: "r"(dst), "l"(src));
}
#define CP_COMMIT() asm volatile("cp.async.commit_group;" ::: "memory")
#define CP_WAIT0()  asm volatile("cp.async.wait_group 0;" ::: "memory")

// ---------------------------------------------------------------------------
// Kernel 0: adj -> bitmask
// ---------------------------------------------------------------------------
__global__ __launch_bounds__(64) void adjbits_kernel(const int* __restrict__ adj)
{
    const int row = blockIdx.x, w = threadIdx.x;
    const int4* p = (const int4*)(adj + (size_t)row * NN + w * 32);
    uint32_t bits = 0;
#pragma unroll
    for (int q = 0; q < 8; q++) {
        int4 v = __ldg(p + q);
        bits |= (v.x ? 1u : 0u) << (q * 4 + 0);
        bits |= (v.y ? 1u : 0u) << (q * 4 + 1);
        bits |= (v.z ? 1u : 0u) << (q * 4 + 2);
        bits |= (v.w ? 1u : 0u) << (q * 4 + 3);
    }
    g_adjbits[row * 64 + w] = bits;
}

// ---------------------------------------------------------------------------
// Kernel 1 (fused, R10 shape): Wh tile GEMM + B-fragment emit + el/er exps.
// ---------------------------------------------------------------------------
__global__ __launch_bounds__(256) void wh_fused(const float* __restrict__ hsrc,
                                                const float* __restrict__ Ww,
                                                const float* __restrict__ Wb,
                                                const float* __restrict__ attn_w)
{
    __shared__ float Bs[32][128];    // Ww^T slab (per kb)
    __shared__ float Whs[32][128];   // output tile
    const int t     = threadIdx.x;
    const int grow0 = blockIdx.x * 32;
    const int col   = (t & 31) * 4;
    const int rl0   = (t >> 5) * 4;

    float acc[4][4];
#pragma unroll
    for (int r = 0; r < 4; r++)
#pragma unroll
        for (int c = 0; c < 4; c++) acc[r][c] = 0.f;

    const float* hr0 = hsrc + (size_t)(grow0 + rl0 + 0) * FIN;
    const float* hr1 = hsrc + (size_t)(grow0 + rl0 + 1) * FIN;
    const float* hr2 = hsrc + (size_t)(grow0 + rl0 + 2) * FIN;
    const float* hr3 = hsrc + (size_t)(grow0 + rl0 + 3) * FIN;

    for (int kb = 0; kb < FIN; kb += 32) {
        {
            int o = t >> 1, kh = (t & 1) * 16;
#pragma unroll
            for (int s2 = 0; s2 < 4; s2++) {
                float4 v = __ldg((const float4*)(Ww + (size_t)o * FIN + kb + kh + s2 * 4));
                Bs[kh + s2 * 4 + 0][o] = v.x;
                Bs[kh + s2 * 4 + 1][o] = v.y;
                Bs[kh + s2 * 4 + 2][o] = v.z;
                Bs[kh + s2 * 4 + 3][o] = v.w;
            }
        }
        __syncthreads();
#pragma unroll
        for (int k4 = 0; k4 < 32; k4 += 4) {
            float4 a0 = __ldg((const float4*)(hr0 + kb + k4));
            float4 a1 = __ldg((const float4*)(hr1 + kb + k4));
            float4 a2 = __ldg((const float4*)(hr2 + kb + k4));
            float4 a3 = __ldg((const float4*)(hr3 + kb + k4));
            float4 b0 = *(const float4*)&Bs[k4 + 0][col];
            float4 b1 = *(const float4*)&Bs[k4 + 1][col];
            float4 b2 = *(const float4*)&Bs[k4 + 2][col];
            float4 b3 = *(const float4*)&Bs[k4 + 3][col];
#define FMA4(ar, bv) \
            acc[0][0] += a0.ar * bv.x; acc[0][1] += a0.ar * bv.y; \
            acc[0][2] += a0.ar * bv.z; acc[0][3] += a0.ar * bv.w; \
            acc[1][0] += a1.ar * bv.x; acc[1][1] += a1.ar * bv.y; \
            acc[1][2] += a1.ar * bv.z; acc[1][3] += a1.ar * bv.w; \
            acc[2][0] += a2.ar * bv.x; acc[2][1] += a2.ar * bv.y; \
            acc[2][2] += a2.ar * bv.z; acc[2][3] += a2.ar * bv.w; \
            acc[3][0] += a3.ar * bv.x; acc[3][1] += a3.ar * bv.y; \
            acc[3][2] += a3.ar * bv.z; acc[3][3] += a3.ar * bv.w;
            FMA4(x, b0) FMA4(y, b1) FMA4(z, b2) FMA4(w, b3)
#undef FMA4
        }
        __syncthreads();
    }

    {
        float4 bias = __ldg((const float4*)(Wb + col));
#pragma unroll
        for (int r = 0; r < 4; r++) {
            float4 o4 = make_float4(acc[r][0] + bias.x, acc[r][1] + bias.y,
                                    acc[r][2] + bias.z, acc[r][3] + bias.w);
            *(float4*)&Whs[rl0 + r][col] = o4;
        }
    }
    __syncthreads();

    const int b  = grow0 >> 11;
    const int n0 = grow0 & (NN - 1);

    // (a) emit B-fragments (tf32)
    {
        const size_t base = ((size_t)b * (NN / 32) + (n0 >> 5)) * 1024;
#pragma unroll
        for (int q = 0; q < 4; q++) {
            const int s    = q * 256 + t;
            const int lane = s & 31;
            const int ntp  = (s >> 5) & 7;
            const int ks   = s >> 8;
            const int jl   = ks * 8 + (lane & 3);
            const int o0   = ntp * 16 + (lane >> 2);
            g_Bfrag4[base + s] = make_uint4(f2tf32(Whs[jl][o0]),
                                            f2tf32(Whs[jl + 4][o0]),
                                            f2tf32(Whs[jl][o0 + 8]),
                                            f2tf32(Whs[jl + 4][o0 + 8]));
        }
    }

    // (b) el/er dots + exps (exact fp32)
    {
        const int w    = t >> 5;
        const int lane = t & 31;
        float4 al[HH], ar[HH];
#pragma unroll
        for (int hh = 0; hh < HH; hh++) {
            al[hh] = __ldg((const float4*)(attn_w + hh * 2 * FOUT + lane * 4));
            ar[hh] = __ldg((const float4*)(attn_w + hh * 2 * FOUT + FOUT + lane * 4));
        }
#pragma unroll
        for (int r = 0; r < 4; r++) {
            const int rowl = w * 4 + r;
            const int n    = n0 + rowl;
            float4 v = *(const float4*)&Whs[rowl][lane * 4];
#pragma unroll
            for (int hh = 0; hh < HH; hh++) {
                float sl = v.x * al[hh].x + v.y * al[hh].y
                         + v.z * al[hh].z + v.w * al[hh].w;
                float sr = v.x * ar[hh].x + v.y * ar[hh].y
                         + v.z * ar[hh].z + v.w * ar[hh].w;
#pragma unroll
                for (int off = 16; off > 0; off >>= 1) {
                    sl += __shfl_xor_sync(0xffffffffu, sl, off);
                    sr += __shfl_xor_sync(0xffffffffu, sr, off);
                }
                if (lane == 0) {
                    g_iAC[(b * HH + hh) * NN + n] =
                        make_float2(expf(sl), expf(NEG * sl));
                    g_jEFi[((size_t)(b * NN + n)) * HH + hh] =
                        make_float2(expf(sr), expf(NEG * sr));
                }
            }
        }
    }
}

// ---------------------------------------------------------------------------
// Kernel 2: Z pre-pass (smem-tiled j-stream, max-trick).
// ---------------------------------------------------------------------------
__device__ __forceinline__ uint32_t zswz(uint32_t a) {
    return a ^ (((a >> 10) & 7u) << 5);
}
__global__ __launch_bounds__(256) void zsum_kernel()
{
    __shared__ float4 jef[512];
    __shared__ float  zr[32][4][8];
    const int t  = threadIdx.x;
    const int b  = blockIdx.y;
    const int i0 = blockIdx.x * 32;
    const int i  = t >> 3, jq = t & 7;
    const int gi = i0 + i;

    float2 AC[4];
#pragma unroll
    for (int h = 0; h < HH; h++) AC[h] = __ldg(&g_iAC[(b * HH + h) * NN + gi]);

    float z0 = 0.f, z1 = 0.f, z2 = 0.f, z3 = 0.f;
    const float4*   src4 = (const float4*)(g_jEFi + (size_t)b * NN * HH);
    const uint32_t* mrow = g_adjbits + (size_t)gi * 64;
    char* jefc = (char*)jef;

    for (int c0 = 0; c0 < NN; c0 += 256) {
        __syncthreads();
        {
            float4 v0 = __ldg(src4 + (size_t)(c0 + t) * 2);
            float4 v1 = __ldg(src4 + (size_t)(c0 + t) * 2 + 1);
            uint32_t a = zswz((uint32_t)t * 32u);
            *(float4*)(jefc + a)      = v0;
            *(float4*)(jefc + a + 16) = v1;
        }
        __syncthreads();

        const uint32_t mw = __ldg(mrow + (c0 >> 5) + jq);
#pragma unroll 8
        for (int e = 0; e < 32; e++) {
            if ((mw >> e) & 1u) {
                uint32_t a = zswz((uint32_t)(jq * 32 + e) * 32u);
                float4 q01 = *(const float4*)(jefc + a);
                float4 q23 = *(const float4*)(jefc + a + 16);
                z0 += fmaxf(AC[0].x * q01.x, AC[0].y * q01.y);
                z1 += fmaxf(AC[1].x * q01.z, AC[1].y * q01.w);
                z2 += fmaxf(AC[2].x * q23.x, AC[2].y * q23.y);
                z3 += fmaxf(AC[3].x * q23.z, AC[3].y * q23.w);
            }
        }
    }
    __syncthreads();
    zr[i][0][jq] = z0; zr[i][1][jq] = z1; zr[i][2][jq] = z2; zr[i][3][jq] = z3;
    __syncthreads();

    if (t < 128) {
        const int ii = t >> 2, h = t & 3;
        float Z = 0.f;
#pragma unroll
        for (int g = 0; g < 8; g++) Z += zr[ii][h][g];
        float2 ac  = __ldg(&g_iAC[(b * HH + h) * NN + i0 + ii]);
        float  inv = (Z > 0.f) ? 0.25f / Z : 0.f;
        g_irow[(b * HH + h) * NN + i0 + ii] = make_float2(ac.x * inv, ac.y * inv);
    }
}

// ---------------------------------------------------------------------------
// Kernel 3 (main): split-K P_avg @ Wh. Grid (64, 4, 2) = 512 CTAs.
// CTA z handles j in [z*1024, z*1024+1024); writes g_part[z].
// Consume = R10 shape (warp tile m32n32, full K per iter).
// ---------------------------------------------------------------------------
#define SM_A(mt, ks, ln)     (((mt) * 4 + (ks)) * 32 + (ln))
#define SM_B(p, ks, ntp, ln) ((p) * 1024 + (ks) * 256 + (ntp) * 32 + (ln))
#define OFF_BF 4096
#define OFF_JP 36864
#define SMEM_BYTES 38912

__global__ __launch_bounds__(256, 3) void gat_main_mma()
{
    extern __shared__ char smem[];
    uint4*  Af  = (uint4*)smem;
    uint4*  Bf  = (uint4*)(smem + OFF_BF);
    float4* JPf = (float4*)(smem + OFF_JP);
    const uint32_t Bf_sa = (uint32_t)__cvta_generic_to_shared(Bf);
    const uint32_t JP_sa = (uint32_t)__cvta_generic_to_shared(JPf);

    const int t    = threadIdx.x;
    const int w    = t >> 5;
    const int lane = t & 31;
    const int mw   = w >> 2;            // m16 tile (gen + consume)
    const int nw   = w & 3;             // consume: 32-col group; gen: ks
    const int b    = blockIdx.y;
    const int i0   = blockIdx.x * 32;
    const int z    = blockIdx.z;        // split-K half
    const int jt0  = z * NIH;           // first 32-j tile index

    const int r = lane >> 2;
    const int c = lane & 3;

    const int gia = i0 + mw * 16 + r;
    const int gib = gia + 8;

    float2 RA[4], RB[4];
#pragma unroll
    for (int h = 0; h < HH; h++) {
        RA[h] = __ldg(&g_irow[(b * HH + h) * NN + gia]);
        RB[h] = __ldg(&g_irow[(b * HH + h) * NN + gib]);
    }
    const uint32_t* mba   = g_adjbits + (size_t)gia * 64 + jt0;
    const uint32_t* mbb   = g_adjbits + (size_t)gib * 64 + jt0;
    const uint4*    bbase = g_Bfrag4 + (size_t)b * (NN / 32) * 1024
                          + (size_t)jt0 * 1024;
    const float4*   jsrc  = (const float4*)(g_jEFi + (size_t)b * NN * HH)
                          + (size_t)jt0 * 64;

    float acc[4][4];
#pragma unroll
    for (int n = 0; n < 4; n++)
#pragma unroll
        for (int k = 0; k < 4; k++) acc[n][k] = 0.f;

    auto stage = [&](int jn, int q) {
        const uint4* src = bbase + (size_t)jn * 1024;
        const uint32_t bdst = Bf_sa + (uint32_t)q * 16384u;
#pragma unroll
        for (int k4 = 0; k4 < 4; k4++)
            cp_async16(bdst + (uint32_t)(k4 * 256 + t) * 16u, src + k4 * 256 + t);
        if (t < 64)
            cp_async16(JP_sa + (uint32_t)(q * 64 + t) * 16u, jsrc + jn * 64 + t);
        CP_COMMIT();
    };

    // each warp generates ONE fragment: (mt = mw, ks = nw)
    auto agen = [&](int p, uint32_t ma, uint32_t mb2) {
        const float4* JP = JPf + p * 64;
        const int jA = nw * 8 + c;
        float4 a01 = JP[jA * 2],       a23 = JP[jA * 2 + 1];
        float4 b01 = JP[(jA + 4) * 2], b23 = JP[(jA + 4) * 2 + 1];

        float vaA = (fmaxf(RA[0].x * a01.x, RA[0].y * a01.y)
                   + fmaxf(RA[1].x * a01.z, RA[1].y * a01.w))
                  + (fmaxf(RA[2].x * a23.x, RA[2].y * a23.y)
                   + fmaxf(RA[3].x * a23.z, RA[3].y * a23.w));
        float vbA = (fmaxf(RB[0].x * a01.x, RB[0].y * a01.y)
                   + fmaxf(RB[1].x * a01.z, RB[1].y * a01.w))
                  + (fmaxf(RB[2].x * a23.x, RB[2].y * a23.y)
                   + fmaxf(RB[3].x * a23.z, RB[3].y * a23.w));
        float vaB = (fmaxf(RA[0].x * b01.x, RA[0].y * b01.y)
                   + fmaxf(RA[1].x * b01.z, RA[1].y * b01.w))
                  + (fmaxf(RA[2].x * b23.x, RA[2].y * b23.y)
                   + fmaxf(RA[3].x * b23.z, RA[3].y * b23.w));
        float vbB = (fmaxf(RB[0].x * b01.x, RB[0].y * b01.y)
                   + fmaxf(RB[1].x * b01.z, RB[1].y * b01.w))
                  + (fmaxf(RB[2].x * b23.x, RB[2].y * b23.y)
                   + fmaxf(RB[3].x * b23.z, RB[3].y * b23.w));

        const int sh = nw * 8 + c;
        vaA = ((ma  >> sh)       & 1u) ? vaA : 0.f;
        vbA = ((mb2 >> sh)       & 1u) ? vbA : 0.f;
        vaB = ((ma  >> (sh + 4)) & 1u) ? vaB : 0.f;
        vbB = ((mb2 >> (sh + 4)) & 1u) ? vbB : 0.f;

        Af[SM_A(mw, nw, lane)] =
            make_uint4(f2tf32(vaA), f2tf32(vbA), f2tf32(vaB), f2tf32(vbB));
    };

    auto consume = [&](int p) {
#pragma unroll
        for (int ks = 0; ks < 4; ks++) {
            uint4 a  = Af[SM_A(mw, ks, lane)];
            uint4 b0 = Bf[SM_B(p, ks, nw * 2 + 0, lane)];
            uint4 b1 = Bf[SM_B(p, ks, nw * 2 + 1, lane)];
            mma_tf32(acc[0][0], acc[0][1], acc[0][2], acc[0][3],
                     a.x, a.y, a.z, a.w, b0.x, b0.y);
            mma_tf32(acc[1][0], acc[1][1], acc[1][2], acc[1][3],
                     a.x, a.y, a.z, a.w, b0.z, b0.w);
            mma_tf32(acc[2][0], acc[2][1], acc[2][2], acc[2][3],
                     a.x, a.y, a.z, a.w, b1.x, b1.y);
            mma_tf32(acc[3][0], acc[3][1], acc[3][2], acc[3][3],
                     a.x, a.y, a.z, a.w, b1.z, b1.w);
        }
    };

    // prologue
    stage(0, 0);
    uint32_t maC = __ldg(mba + 0);
    uint32_t mbC = __ldg(mbb + 0);
    CP_WAIT0();
    __syncthreads();

    // pipelined mainloop over this CTA's 32 tiles
    for (int jt = 0; jt < NIH; jt++) {
        const int p = jt & 1, q = p ^ 1;

        if (jt + 1 < NIH) stage(jt + 1, q);

        agen(p, maC, mbC);
        __syncthreads();                 // Af visible

        consume(p);

        if (jt + 1 < NIH) {
            maC = __ldg(mba + jt + 1);
            mbC = __ldg(mbb + jt + 1);
            CP_WAIT0();
        }
        __syncthreads();                 // buffer q ready; Af free
    }

    // epilogue: write split-K partials (no ReLU yet)
    float* part = g_part[z];
    const int rowa = i0 + mw * 16 + r;
#pragma unroll
    for (int nt = 0; nt < 4; nt++) {
        const int col = nw * 32 + nt * 8 + c * 2;
        float* op = part + ((size_t)(b * NN + rowa)) * FOUT + col;
        *(float2*)op = make_float2(acc[nt][0], acc[nt][1]);
        *(float2*)(op + 8 * FOUT) = make_float2(acc[nt][2], acc[nt][3]);
    }
}

// ---------------------------------------------------------------------------
// Kernel 4: combine split-K partials, ReLU, store.
// ---------------------------------------------------------------------------
__global__ __launch_bounds__(256) void combine_kernel(float* __restrict__ out)
{
    const size_t idx = ((size_t)blockIdx.x * 256 + threadIdx.x) * 4;
    float4 a = *(const float4*)(g_part[0] + idx);
    float4 bq = *(const float4*)(g_part[1] + idx);
    float4 o = make_float4(fmaxf(a.x + bq.x, 0.f), fmaxf(a.y + bq.y, 0.f),
                           fmaxf(a.z + bq.z, 0.f), fmaxf(a.w + bq.w, 0.f));
    *(float4*)(out + idx) = o;
}

// ---------------------------------------------------------------------------
extern "C" void kernel_launch(void* const* d_in, const int* in_sizes, int n_in,
                              void* d_out, int out_size)
{
    const float* h      = (const float*)d_in[0];
    const int*   adj    = (const int*)d_in[1];
    const float* W_w    = (const float*)d_in[2];
    const float* W_b    = (const float*)d_in[3];
    const float* attn_w = (const float*)d_in[4];
    float* out = (float*)d_out;

    adjbits_kernel<<<NN, 64>>>(adj);
    wh_fused<<<(Bb * NN) / 32, 256>>>(h, W_w, W_b, attn_w);
    zsum_kernel<<<dim3(NN / 32, Bb), 256>>>();

    cudaFuncSetAttribute(gat_main_mma,
                         cudaFuncAttributeMaxDynamicSharedMemorySize, SMEM_BYTES);
    gat_main_mma<<<dim3(NN / 32, Bb, 2), 256, SMEM_BYTES>>>();

    combine_kernel<<<(Bb * NN * FOUT) / 1024, 256>>>(out);
}

// round 13
// speedup vs baseline: 1.0487x; 1.0344x over previous
#include <cuda_runtime.h>
#include <cstdint>

#define Bb   4
#define NN   2048
#define FIN  256
#define FOUT 128
#define HH   4
#define NEG  0.2f
#define TKI  32          // j per mainloop iteration
#define NI   (NN / TKI)  // 64

// ---------------------------------------------------------------------------
// scratch (no cudaMalloc allowed)
// ---------------------------------------------------------------------------
__device__ float2   g_iAC[Bb * HH * NN];         // (e^el, e^.2el) per (b,h,i)
__device__ float2   g_jEFi[Bb * NN * HH];        // (e^er, e^.2er), [(b*NN+n)*4+h]
__device__ float2   g_irow[Bb * HH * NN];        // prescaled (A*0.25/Z, C*0.25/Z)
__device__ uint32_t g_adjbits[NN * 64];          // 512 KB
__device__ uint4    g_Bfrag4[Bb * (NN / 32) * 1024]; // Wh B-fragments (tf32)

// ---------------------------------------------------------------------------
__device__ __forceinline__ uint32_t f2tf32(float f) {
    uint32_t u;
    asm("cvt.rna.tf32.f32 %0, %1;" : "=r"(u) : "f"(f));
    return u;
}
__device__ __forceinline__ void mma_tf32(float& c0, float& c1, float& c2, float& c3,
                                         uint32_t a0, uint32_t a1, uint32_t a2, uint32_t a3,
                                         uint32_t b0, uint32_t b1) {
    asm volatile("mma.sync.aligned.m16n8k8.row.col.f32.tf32.tf32.f32 "
                 "{%0,%1,%2,%3}, {%4,%5,%6,%7}, {%8,%9}, {%0,%1,%2,%3};"
                 : "+f"(c0), "+f"(c1), "+f"(c2), "+f"(c3)
                 : "r"(a0), "r"(a1), "r"(a2), "r"(a3), "r"(b0), "r"(b1));
}
__device__ __forceinline__ void cp_async16(uint32_t dst, const void* src) {
    asm volatile("cp.async.cg.shared.global [%0], [%1], 16;" :: "r"(dst), "l"(src));
}
#define CP_COMMIT()  asm volatile("cp.async.commit_group;" ::: "memory")
#define CP_WAIT(n)   asm volatile("cp.async.wait_group %0;" :: "n"(n) : "memory")

// ---------------------------------------------------------------------------
// Kernel 0: adj -> bitmask
// ---------------------------------------------------------------------------
__global__ __launch_bounds__(64) void adjbits_kernel(const int* __restrict__ adj)
{
    const int row = blockIdx.x, w = threadIdx.x;
    const int4* p = (const int4*)(adj + (size_t)row * NN + w * 32);
    uint32_t bits = 0;
#pragma unroll
    for (int q = 0; q < 8; q++) {
        int4 v = __ldg(p + q);
        bits |= (v.x ? 1u : 0u) << (q * 4 + 0);
        bits |= (v.y ? 1u : 0u) << (q * 4 + 1);
        bits |= (v.z ? 1u : 0u) << (q * 4 + 2);
        bits |= (v.w ? 1u : 0u) << (q * 4 + 3);
    }
    g_adjbits[row * 64 + w] = bits;
}

// ---------------------------------------------------------------------------
// Kernel 1 (fused, R10 shape): Wh tile GEMM + B-fragment emit + el/er exps.
// ---------------------------------------------------------------------------
__global__ __launch_bounds__(256) void wh_fused(const float* __restrict__ hsrc,
                                                const float* __restrict__ Ww,
                                                const float* __restrict__ Wb,
                                                const float* __restrict__ attn_w)
{
    __shared__ float Bs[32][128];    // Ww^T slab (per kb)
    __shared__ float Whs[32][128];   // output tile
    const int t     = threadIdx.x;
    const int grow0 = blockIdx.x * 32;
    const int col   = (t & 31) * 4;
    const int rl0   = (t >> 5) * 4;

    float acc[4][4];
#pragma unroll
    for (int r = 0; r < 4; r++)
#pragma unroll
        for (int c = 0; c < 4; c++) acc[r][c] = 0.f;

    const float* hr0 = hsrc + (size_t)(grow0 + rl0 + 0) * FIN;
    const float* hr1 = hsrc + (size_t)(grow0 + rl0 + 1) * FIN;
    const float* hr2 = hsrc + (size_t)(grow0 + rl0 + 2) * FIN;
    const float* hr3 = hsrc + (size_t)(grow0 + rl0 + 3) * FIN;

    for (int kb = 0; kb < FIN; kb += 32) {
        {
            int o = t >> 1, kh = (t & 1) * 16;
#pragma unroll
            for (int s2 = 0; s2 < 4; s2++) {
                float4 v = __ldg((const float4*)(Ww + (size_t)o * FIN + kb + kh + s2 * 4));
                Bs[kh + s2 * 4 + 0][o] = v.x;
                Bs[kh + s2 * 4 + 1][o] = v.y;
                Bs[kh + s2 * 4 + 2][o] = v.z;
                Bs[kh + s2 * 4 + 3][o] = v.w;
            }
        }
        __syncthreads();
#pragma unroll
        for (int k4 = 0; k4 < 32; k4 += 4) {
            float4 a0 = __ldg((const float4*)(hr0 + kb + k4));
            float4 a1 = __ldg((const float4*)(hr1 + kb + k4));
            float4 a2 = __ldg((const float4*)(hr2 + kb + k4));
            float4 a3 = __ldg((const float4*)(hr3 + kb + k4));
            float4 b0 = *(const float4*)&Bs[k4 + 0][col];
            float4 b1 = *(const float4*)&Bs[k4 + 1][col];
            float4 b2 = *(const float4*)&Bs[k4 + 2][col];
            float4 b3 = *(const float4*)&Bs[k4 + 3][col];
#define FMA4(ar, bv) \
            acc[0][0] += a0.ar * bv.x; acc[0][1] += a0.ar * bv.y; \
            acc[0][2] += a0.ar * bv.z; acc[0][3] += a0.ar * bv.w; \
            acc[1][0] += a1.ar * bv.x; acc[1][1] += a1.ar * bv.y; \
            acc[1][2] += a1.ar * bv.z; acc[1][3] += a1.ar * bv.w; \
            acc[2][0] += a2.ar * bv.x; acc[2][1] += a2.ar * bv.y; \
            acc[2][2] += a2.ar * bv.z; acc[2][3] += a2.ar * bv.w; \
            acc[3][0] += a3.ar * bv.x; acc[3][1] += a3.ar * bv.y; \
            acc[3][2] += a3.ar * bv.z; acc[3][3] += a3.ar * bv.w;
            FMA4(x, b0) FMA4(y, b1) FMA4(z, b2) FMA4(w, b3)
#undef FMA4
        }
        __syncthreads();
    }

    {
        float4 bias = __ldg((const float4*)(Wb + col));
#pragma unroll
        for (int r = 0; r < 4; r++) {
            float4 o4 = make_float4(acc[r][0] + bias.x, acc[r][1] + bias.y,
                                    acc[r][2] + bias.z, acc[r][3] + bias.w);
            *(float4*)&Whs[rl0 + r][col] = o4;
        }
    }
    __syncthreads();

    const int b  = grow0 >> 11;
    const int n0 = grow0 & (NN - 1);

    // (a) emit B-fragments (tf32)
    {
        const size_t base = ((size_t)b * (NN / 32) + (n0 >> 5)) * 1024;
#pragma unroll
        for (int q = 0; q < 4; q++) {
            const int s    = q * 256 + t;
            const int lane = s & 31;
            const int ntp  = (s >> 5) & 7;
            const int ks   = s >> 8;
            const int jl   = ks * 8 + (lane & 3);
            const int o0   = ntp * 16 + (lane >> 2);
            g_Bfrag4[base + s] = make_uint4(f2tf32(Whs[jl][o0]),
                                            f2tf32(Whs[jl + 4][o0]),
                                            f2tf32(Whs[jl][o0 + 8]),
                                            f2tf32(Whs[jl + 4][o0 + 8]));
        }
    }

    // (b) el/er dots + exps (exact fp32)
    {
        const int w    = t >> 5;
        const int lane = t & 31;
        float4 al[HH], ar[HH];
#pragma unroll
        for (int hh = 0; hh < HH; hh++) {
            al[hh] = __ldg((const float4*)(attn_w + hh * 2 * FOUT + lane * 4));
            ar[hh] = __ldg((const float4*)(attn_w + hh * 2 * FOUT + FOUT + lane * 4));
        }
#pragma unroll
        for (int r = 0; r < 4; r++) {
            const int rowl = w * 4 + r;
            const int n    = n0 + rowl;
            float4 v = *(const float4*)&Whs[rowl][lane * 4];
#pragma unroll
            for (int hh = 0; hh < HH; hh++) {
                float sl = v.x * al[hh].x + v.y * al[hh].y
                         + v.z * al[hh].z + v.w * al[hh].w;
                float sr = v.x * ar[hh].x + v.y * ar[hh].y
                         + v.z * ar[hh].z + v.w * ar[hh].w;
#pragma unroll
                for (int off = 16; off > 0; off >>= 1) {
                    sl += __shfl_xor_sync(0xffffffffu, sl, off);
                    sr += __shfl_xor_sync(0xffffffffu, sr, off);
                }
                if (lane == 0) {
                    g_iAC[(b * HH + hh) * NN + n] =
                        make_float2(expf(sl), expf(NEG * sl));
                    g_jEFi[((size_t)(b * NN + n)) * HH + hh] =
                        make_float2(expf(sr), expf(NEG * sr));
                }
            }
        }
    }
}

// ---------------------------------------------------------------------------
// Kernel 2: Z pre-pass (smem-tiled j-stream, max-trick).
// ---------------------------------------------------------------------------
__device__ __forceinline__ uint32_t zswz(uint32_t a) {
    return a ^ (((a >> 10) & 7u) << 5);
}
__global__ __launch_bounds__(256) void zsum_kernel()
{
    __shared__ float4 jef[512];
    __shared__ float  zr[32][4][8];
    const int t  = threadIdx.x;
    const int b  = blockIdx.y;
    const int i0 = blockIdx.x * 32;
    const int i  = t >> 3, jq = t & 7;
    const int gi = i0 + i;

    float2 AC[4];
#pragma unroll
    for (int h = 0; h < HH; h++) AC[h] = __ldg(&g_iAC[(b * HH + h) * NN + gi]);

    float z0 = 0.f, z1 = 0.f, z2 = 0.f, z3 = 0.f;
    const float4*   src4 = (const float4*)(g_jEFi + (size_t)b * NN * HH);
    const uint32_t* mrow = g_adjbits + (size_t)gi * 64;
    char* jefc = (char*)jef;

    for (int c0 = 0; c0 < NN; c0 += 256) {
        __syncthreads();
        {
            float4 v0 = __ldg(src4 + (size_t)(c0 + t) * 2);
            float4 v1 = __ldg(src4 + (size_t)(c0 + t) * 2 + 1);
            uint32_t a = zswz((uint32_t)t * 32u);
            *(float4*)(jefc + a)      = v0;
            *(float4*)(jefc + a + 16) = v1;
        }
        __syncthreads();

        const uint32_t mw = __ldg(mrow + (c0 >> 5) + jq);
#pragma unroll 8
        for (int e = 0; e < 32; e++) {
            if ((mw >> e) & 1u) {
                uint32_t a = zswz((uint32_t)(jq * 32 + e) * 32u);
                float4 q01 = *(const float4*)(jefc + a);
                float4 q23 = *(const float4*)(jefc + a + 16);
                z0 += fmaxf(AC[0].x * q01.x, AC[0].y * q01.y);
                z1 += fmaxf(AC[1].x * q01.z, AC[1].y * q01.w);
                z2 += fmaxf(AC[2].x * q23.x, AC[2].y * q23.y);
                z3 += fmaxf(AC[3].x * q23.z, AC[3].y * q23.w);
            }
        }
    }
    __syncthreads();
    zr[i][0][jq] = z0; zr[i][1][jq] = z1; zr[i][2][jq] = z2; zr[i][3][jq] = z3;
    __syncthreads();

    if (t < 128) {
        const int ii = t >> 2, h = t & 3;
        float Z = 0.f;
#pragma unroll
        for (int g = 0; g < 8; g++) Z += zr[ii][h][g];
        float2 ac  = __ldg(&g_iAC[(b * HH + h) * NN + i0 + ii]);
        float  inv = (Z > 0.f) ? 0.25f / Z : 0.f;
        g_irow[(b * HH + h) * NN + i0 + ii] = make_float2(ac.x * inv, ac.y * inv);
    }
}

// ---------------------------------------------------------------------------
// Kernel 3 (main): P_avg @ Wh via mma.sync tf32, M=32, TK=32/iter.
// 3-STAGE cp.async pipeline (wait_group 1): tiles jt+1 and jt+2 in flight.
// smem 55KB: Af 4K | Bf 3x16K | JP 3x1K. 3 CTAs/SM (reg-limited).
// ---------------------------------------------------------------------------
#define SM_A(mt, ks, ln)     (((mt) * 4 + (ks)) * 32 + (ln))
#define SM_B(p, ks, ntp, ln) ((p) * 1024 + (ks) * 256 + (ntp) * 32 + (ln))
#define OFF_BF 4096
#define OFF_JP (4096 + 3 * 16384)     // 53248
#define SMEM_BYTES (OFF_JP + 3 * 1024)  // 56320

__global__ __launch_bounds__(256, 3) void gat_main_mma(float* __restrict__ out)
{
    extern __shared__ char smem[];
    uint4*  Af  = (uint4*)smem;
    uint4*  Bf  = (uint4*)(smem + OFF_BF);
    float4* JPf = (float4*)(smem + OFF_JP);
    const uint32_t Bf_sa = (uint32_t)__cvta_generic_to_shared(Bf);
    const uint32_t JP_sa = (uint32_t)__cvta_generic_to_shared(JPf);

    const int t    = threadIdx.x;
    const int w    = t >> 5;
    const int lane = t & 31;
    const int mw   = w >> 2;            // m16 tile (gen + consume)
    const int nw   = w & 3;             // consume: 32-col group; gen: ks
    const int b    = blockIdx.y;
    const int i0   = blockIdx.x * 32;

    const int r = lane >> 2;
    const int c = lane & 3;

    const int gia = i0 + mw * 16 + r;
    const int gib = gia + 8;

    float2 RA[4], RB[4];
#pragma unroll
    for (int h = 0; h < HH; h++) {
        RA[h] = __ldg(&g_irow[(b * HH + h) * NN + gia]);
        RB[h] = __ldg(&g_irow[(b * HH + h) * NN + gib]);
    }
    const uint32_t* mba   = g_adjbits + (size_t)gia * 64;
    const uint32_t* mbb   = g_adjbits + (size_t)gib * 64;
    const uint4*    bbase = g_Bfrag4 + (size_t)b * (NN / 32) * 1024;
    const float4*   jsrc  = (const float4*)(g_jEFi + (size_t)b * NN * HH);

    float acc[4][4];
#pragma unroll
    for (int n = 0; n < 4; n++)
#pragma unroll
        for (int k = 0; k < 4; k++) acc[n][k] = 0.f;

    auto stage = [&](int jn, int q) {
        const uint4* src = bbase + (size_t)jn * 1024;
        const uint32_t bdst = Bf_sa + (uint32_t)q * 16384u;
#pragma unroll
        for (int k4 = 0; k4 < 4; k4++)
            cp_async16(bdst + (uint32_t)(k4 * 256 + t) * 16u, src + k4 * 256 + t);
        if (t < 64)
            cp_async16(JP_sa + (uint32_t)(q * 64 + t) * 16u, jsrc + jn * 64 + t);
        CP_COMMIT();
    };

    // each warp generates ONE fragment: (mt = mw, ks = nw)
    auto agen = [&](int p, uint32_t ma, uint32_t mb2) {
        const float4* JP = JPf + p * 64;
        const int jA = nw * 8 + c;
        float4 a01 = JP[jA * 2],       a23 = JP[jA * 2 + 1];
        float4 b01 = JP[(jA + 4) * 2], b23 = JP[(jA + 4) * 2 + 1];

        float vaA = (fmaxf(RA[0].x * a01.x, RA[0].y * a01.y)
                   + fmaxf(RA[1].x * a01.z, RA[1].y * a01.w))
                  + (fmaxf(RA[2].x * a23.x, RA[2].y * a23.y)
                   + fmaxf(RA[3].x * a23.z, RA[3].y * a23.w));
        float vbA = (fmaxf(RB[0].x * a01.x, RB[0].y * a01.y)
                   + fmaxf(RB[1].x * a01.z, RB[1].y * a01.w))
                  + (fmaxf(RB[2].x * a23.x, RB[2].y * a23.y)
                   + fmaxf(RB[3].x * a23.z, RB[3].y * a23.w));
        float vaB = (fmaxf(RA[0].x * b01.x, RA[0].y * b01.y)
                   + fmaxf(RA[1].x * b01.z, RA[1].y * b01.w))
                  + (fmaxf(RA[2].x * b23.x, RA[2].y * b23.y)
                   + fmaxf(RA[3].x * b23.z, RA[3].y * b23.w));
        float vbB = (fmaxf(RB[0].x * b01.x, RB[0].y * b01.y)
                   + fmaxf(RB[1].x * b01.z, RB[1].y * b01.w))
                  + (fmaxf(RB[2].x * b23.x, RB[2].y * b23.y)
                   + fmaxf(RB[3].x * b23.z, RB[3].y * b23.w));

        const int sh = nw * 8 + c;
        vaA = ((ma  >> sh)       & 1u) ? vaA : 0.f;
        vbA = ((mb2 >> sh)       & 1u) ? vbA : 0.f;
        vaB = ((ma  >> (sh + 4)) & 1u) ? vaB : 0.f;
        vbB = ((mb2 >> (sh + 4)) & 1u) ? vbB : 0.f;

        Af[SM_A(mw, nw, lane)] =
            make_uint4(f2tf32(vaA), f2tf32(vbA), f2tf32(vaB), f2tf32(vbB));
    };

    auto consume = [&](int p) {
#pragma unroll
        for (int ks = 0; ks < 4; ks++) {
            uint4 a  = Af[SM_A(mw, ks, lane)];
            uint4 b0 = Bf[SM_B(p, ks, nw * 2 + 0, lane)];
            uint4 b1 = Bf[SM_B(p, ks, nw * 2 + 1, lane)];
            mma_tf32(acc[0][0], acc[0][1], acc[0][2], acc[0][3],
                     a.x, a.y, a.z, a.w, b0.x, b0.y);
            mma_tf32(acc[1][0], acc[1][1], acc[1][2], acc[1][3],
                     a.x, a.y, a.z, a.w, b0.z, b0.w);
            mma_tf32(acc[2][0], acc[2][1], acc[2][2], acc[2][3],
                     a.x, a.y, a.z, a.w, b1.x, b1.y);
            mma_tf32(acc[3][0], acc[3][1], acc[3][2], acc[3][3],
                     a.x, a.y, a.z, a.w, b1.z, b1.w);
        }
    };

    // prologue: two tiles in flight
    stage(0, 0);
    stage(1, 1);
    uint32_t maC = __ldg(mba + 0);
    uint32_t mbC = __ldg(mbb + 0);
    CP_WAIT(1);                          // tile 0 complete (tile 1 may be in flight)
    __syncthreads();

    // 3-stage pipelined mainloop
    for (int jt = 0; jt < NI; jt++) {
        const int p = jt % 3;

        if (jt + 2 < NI) stage(jt + 2, (jt + 2) % 3);

        agen(p, maC, mbC);
        __syncthreads();                 // Af visible

        consume(p);

        if (jt + 1 < NI) {
            maC = __ldg(mba + jt + 1);
            mbC = __ldg(mbb + jt + 1);
            if (jt + 2 < NI) CP_WAIT(1); // tile jt+1 complete, jt+2 may fly
            else             CP_WAIT(0); // nothing new staged: drain all
        }
        __syncthreads();                 // next buffer ready; Af free
    }

    // epilogue: accumulators are final pre-ReLU outputs
    const int rowa = i0 + mw * 16 + r;
#pragma unroll
    for (int nt = 0; nt < 4; nt++) {
        const int col = nw * 32 + nt * 8 + c * 2;
        float* op = out + ((size_t)(b * NN + rowa)) * FOUT + col;
        *(float2*)op = make_float2(fmaxf(acc[nt][0], 0.f), fmaxf(acc[nt][1], 0.f));
        *(float2*)(op + 8 * FOUT) = make_float2(fmaxf(acc[nt][2], 0.f),
                                                fmaxf(acc[nt][3], 0.f));
    }
}

// ---------------------------------------------------------------------------
extern "C" void kernel_launch(void* const* d_in, const int* in_sizes, int n_in,
                              void* d_out, int out_size)
{
    const float* h      = (const float*)d_in[0];
    const int*   adj    = (const int*)d_in[1];
    const float* W_w    = (const float*)d_in[2];
    const float* W_b    = (const float*)d_in[3];
    const float* attn_w = (const float*)d_in[4];
    float* out = (float*)d_out;

    adjbits_kernel<<<NN, 64>>>(adj);
    wh_fused<<<(Bb * NN) / 32, 256>>>(h, W_w, W_b, attn_w);
    zsum_kernel<<<dim3(NN / 32, Bb), 256>>>();

    cudaFuncSetAttribute(gat_main_mma,
                         cudaFuncAttributeMaxDynamicSharedMemorySize, SMEM_BYTES);
    gat_main_mma<<<dim3(NN / 32, Bb), 256, SMEM_BYTES>>>(out);
}